// round 6
// baseline (speedup 1.0000x reference)
#include <cuda_runtime.h>
#include <cuda_fp16.h>
#include <cstdint>

#define B_    8
#define CIN   256
#define COUT  256
#define CINFO 256
#define LL    32768
#define CHUNK 32                 // l-positions per chunk
#define NCH   (LL / CHUNK)       // 1024 chunks per batch
#define PITCH 12                 // words per (kt,l) row: 8 data + 4 pad
#define KTSZ  (32 * PITCH)       // 384 words per kt slab
#define BUFW  (16 * KTSZ)        // 6144 words per buffer (24 KB)

// ---------------- device scratch ----------------
__device__ float  g_Ain [B_ * CIN * 2];     // [b][i*2 + r]
__device__ float  g_Aout[B_ * 2 * COUT];    // [b][r*256 + o]
__device__ __half g_Weff[B_ * COUT * CIN];  // [b][o][i]

// ---------------- helpers ----------------
__device__ __forceinline__ uint32_t pack_f16x2(float lo, float hi) {
    uint32_t r;  // second source -> low half
    asm("cvt.rn.f16x2.f32 %0, %1, %2;" : "=r"(r) : "f"(hi), "f"(lo));
    return r;
}

__device__ __forceinline__ void mma16816(float* c, const uint32_t* A, uint32_t b0, uint32_t b1) {
    asm volatile(
        "mma.sync.aligned.m16n8k16.row.col.f32.f16.f16.f32 "
        "{%0,%1,%2,%3}, {%4,%5,%6,%7}, {%8,%9}, {%0,%1,%2,%3};"
        : "+f"(c[0]), "+f"(c[1]), "+f"(c[2]), "+f"(c[3])
        : "r"(A[0]), "r"(A[1]), "r"(A[2]), "r"(A[3]), "r"(b0), "r"(b1));
}

// ---------------- prologue 1: adapter vectors ----------------
__global__ void lora_adapters_kernel(const float* __restrict__ g_out,
                                     const float* __restrict__ W_ain,
                                     const float* __restrict__ W_aout) {
    __shared__ float sg[CINFO];
    int bx = blockIdx.x;
    int b = bx >> 6;
    int kbase = (bx & 63) * 8;
    for (int i = threadIdx.x; i < CINFO; i += 128) sg[i] = g_out[b * CINFO + i];
    __syncthreads();
    int w = threadIdx.x >> 5, lane = threadIdx.x & 31;
#pragma unroll
    for (int t = 0; t < 2; ++t) {
        int k = kbase + w * 2 + t;
        const float* wi = W_ain  + (size_t)k * CINFO;
        const float* wo = W_aout + (size_t)k * CINFO;
        float ai = 0.f, ao = 0.f;
#pragma unroll
        for (int i = lane; i < CINFO; i += 32) {
            float gv = sg[i];
            ai += wi[i] * gv;
            ao += wo[i] * gv;
        }
#pragma unroll
        for (int off = 16; off; off >>= 1) {
            ai += __shfl_xor_sync(0xFFFFFFFFu, ai, off);
            ao += __shfl_xor_sync(0xFFFFFFFFu, ao, off);
        }
        if (lane == 0) {
            g_Ain [b * 512 + k] = ai;
            g_Aout[b * 512 + k] = ao;
        }
    }
}

// ---------------- prologue 2: effective weight (fp16) ----------------
__global__ void lora_weff_kernel(const float* __restrict__ W_main) {
    int o = blockIdx.x, b = blockIdx.y, i = threadIdx.x;
    float wm = W_main[o * CIN + i];
    float a0 = g_Ain [b * 512 + i * 2 + 0];
    float a1 = g_Ain [b * 512 + i * 2 + 1];
    float q0 = g_Aout[b * 512 + o];
    float q1 = g_Aout[b * 512 + COUT + o];
    g_Weff[(size_t)b * (COUT * CIN) + o * CIN + i] = __float2half(wm + q0 * a0 + q1 * a1);
}

// ---------------- main persistent GEMM (mma.sync / HMMA) ----------------
// 256 threads / 8 warps. Warp w owns cout rows [32w, 32w+32) (2 m-tiles),
// computes full N=32 (4 n-tiles), K=256 (16 kt) -> 128 MMAs/warp/chunk.
// Weff A fragments live in registers for the whole kernel (128 b32/thread).
//
// SMEM word layout per buffer: idx(kt, l, j') = kt*384 + l*12 + j'
//   j stores k-pair jj (0..7) of kt at j' = (jj&4) | ((jj&3) ^ ((l>>2)&3)).
// Consumer bank proof: per warp, l = nt*8+g covers 8 rows whose bases
// 12l mod 32 = {0,12,24,4,16,28,8,20} are disjoint blocks spaced 4; offsets
// (q ^ f(l)) stay in [0,4) -> 32 distinct banks for b0; b1 adds +4 (still
// distinct). STS is 2-way worst case (lanes l, l+16) - negligible.
__global__ void __launch_bounds__(256, 1)
lora_main_kernel(const float* __restrict__ x, const float* __restrict__ b_main,
                 float* __restrict__ out, int per_batch) {
    extern __shared__ uint32_t sm[];   // 2 * BUFW words = 48 KB
    const int tid = threadIdx.x;
    const int lane = tid & 31;
    const int w = tid >> 5;            // 0..7
    const int cta = blockIdx.x;
    const int b  = cta / per_batch;
    const int jj = cta % per_batch;
    const int s = (jj * NCH) / per_batch;
    const int e = ((jj + 1) * NCH) / per_batch;
    if (s >= e) return;

    const float* xb = x   + (size_t)b * ((size_t)CIN * LL);
    float*       ob = out + (size_t)b * ((size_t)COUT * LL);

    const int obase = w * 32;
    const int g = lane >> 2;     // 0..7
    const int q = lane & 3;      // 0..3

    // ---- A fragments (Weff) resident in registers ----
    uint32_t A0[16][4], A1[16][4];
    {
        const __half* Wb = g_Weff + (size_t)b * (COUT * CIN);
        const uint32_t* r00 = (const uint32_t*)(Wb + (size_t)(obase + g)      * CIN);
        const uint32_t* r01 = (const uint32_t*)(Wb + (size_t)(obase + g + 8)  * CIN);
        const uint32_t* r10 = (const uint32_t*)(Wb + (size_t)(obase + 16 + g) * CIN);
        const uint32_t* r11 = (const uint32_t*)(Wb + (size_t)(obase + 24 + g) * CIN);
#pragma unroll
        for (int kt = 0; kt < 16; ++kt) {
            A0[kt][0] = r00[kt * 8 + q];
            A0[kt][1] = r01[kt * 8 + q];
            A0[kt][2] = r00[kt * 8 + 4 + q];
            A0[kt][3] = r01[kt * 8 + 4 + q];
            A1[kt][0] = r10[kt * 8 + q];
            A1[kt][1] = r11[kt * 8 + q];
            A1[kt][2] = r10[kt * 8 + 4 + q];
            A1[kt][3] = r11[kt * 8 + 4 + q];
        }
    }
    const float bg00 = b_main[obase + g];
    const float bg01 = b_main[obase + 8 + g];
    const float bg10 = b_main[obase + 16 + g];
    const float bg11 = b_main[obase + 24 + g];

    uint32_t packed[16];   // fp16x2 pairs: k-pair j of this warp's 32 cin rows

    // 32 coalesced LDGs (lane = l), packed in two halves to bound live regs
    auto ldg_chunk = [&](int chunk) {
        const float* p = xb + (size_t)chunk * CHUNK + lane;
#pragma unroll
        for (int h = 0; h < 2; ++h) {
            float v0[8], v1[8];
#pragma unroll
            for (int j = 0; j < 8; ++j) {
                int i0 = w * 32 + h * 16 + 2 * j;
                v0[j] = p[(size_t)i0 * LL];
                v1[j] = p[(size_t)(i0 + 1) * LL];
            }
#pragma unroll
            for (int j = 0; j < 8; ++j)
                packed[h * 8 + j] = pack_f16x2(v0[j], v1[j]);
        }
    };

    // swizzled STS: warp w feeds kt = 2w, 2w+1
    auto sts_chunk = [&](int bufsel) {
        uint32_t* d = sm + bufsel * BUFW + lane * PITCH;
        const uint32_t f = ((uint32_t)lane >> 2) & 3;
#pragma unroll
        for (int j = 0; j < 16; ++j) {
            int kt = 2 * w + (j >> 3);
            uint32_t jl = (uint32_t)j & 7;
            uint32_t jp = (jl & 4) | ((jl & 3) ^ f);
            d[kt * KTSZ + jp] = packed[j];
        }
    };

    ldg_chunk(s);
    sts_chunk(0);
    __syncthreads();

    for (int c = s; c < e; ++c) {
        const int cb = (c - s) & 1;
        const bool more = (c + 1) < e;
        if (more) ldg_chunk(c + 1);   // DRAM latency hides under MMA block

        float acc0[4][4], acc1[4][4];
#pragma unroll
        for (int nt = 0; nt < 4; ++nt)
#pragma unroll
            for (int r = 0; r < 4; ++r) { acc0[nt][r] = 0.f; acc1[nt][r] = 0.f; }

        const uint32_t* buf = sm + cb * BUFW;
#pragma unroll
        for (int nt = 0; nt < 4; ++nt) {
            const int l = nt * 8 + g;
            const uint32_t* row = buf + l * PITCH + (q ^ ((l >> 2) & 3));
#pragma unroll
            for (int kt = 0; kt < 16; ++kt) {
                uint32_t b0 = row[kt * KTSZ];
                uint32_t b1 = row[kt * KTSZ + 4];
                mma16816(acc0[nt], A0[kt], b0, b1);
                mma16816(acc1[nt], A1[kt], b0, b1);
            }
        }

        if (more) sts_chunk(cb ^ 1);

        // epilogue: bias + coalesced float2 stores
        {
            const size_t lc = (size_t)c * CHUNK + 2 * q;
            float* o00 = ob + (size_t)(obase + g)      * LL + lc;
            float* o01 = ob + (size_t)(obase + g + 8)  * LL + lc;
            float* o10 = ob + (size_t)(obase + 16 + g) * LL + lc;
            float* o11 = ob + (size_t)(obase + 24 + g) * LL + lc;
#pragma unroll
            for (int nt = 0; nt < 4; ++nt) {
                *(float2*)(o00 + nt * 8) = make_float2(acc0[nt][0] + bg00, acc0[nt][1] + bg00);
                *(float2*)(o01 + nt * 8) = make_float2(acc0[nt][2] + bg01, acc0[nt][3] + bg01);
                *(float2*)(o10 + nt * 8) = make_float2(acc1[nt][0] + bg10, acc1[nt][1] + bg10);
                *(float2*)(o11 + nt * 8) = make_float2(acc1[nt][2] + bg11, acc1[nt][3] + bg11);
            }
        }
        __syncthreads();
    }
}

// ---------------- launch ----------------
extern "C" void kernel_launch(void* const* d_in, const int* in_sizes, int n_in,
                              void* d_out, int out_size) {
    const float* x      = (const float*)d_in[0];
    const float* g_out  = (const float*)d_in[1];
    const float* W_main = (const float*)d_in[2];
    const float* b_main = (const float*)d_in[3];
    const float* W_ain  = (const float*)d_in[4];
    const float* W_aout = (const float*)d_in[5];
    float* out = (float*)d_out;

    int dev = 0, sms = 148;
    cudaGetDevice(&dev);
    cudaDeviceGetAttribute(&sms, cudaDevAttrMultiProcessorCount, dev);
    int per_batch = sms / B_;
    if (per_batch < 1) per_batch = 1;
    if (per_batch > NCH) per_batch = NCH;

    size_t smem = 2ull * BUFW * sizeof(uint32_t);  // 48 KB
    cudaFuncSetAttribute(lora_main_kernel, cudaFuncAttributeMaxDynamicSharedMemorySize, (int)smem);

    lora_adapters_kernel<<<B_ * 64, 128>>>(g_out, W_ain, W_aout);
    lora_weff_kernel<<<dim3(COUT, B_), CIN>>>(W_main);
    lora_main_kernel<<<per_batch * B_, 256, smem>>>(x, b_main, out, per_batch);
}

// round 7
// speedup vs baseline: 1.2700x; 1.2700x over previous
#include <cuda_runtime.h>
#include <cuda_fp16.h>
#include <cstdint>

#define B_    8
#define CIN   256
#define COUT  256
#define CINFO 256
#define LL    32768
#define CHUNK 32                 // l-positions per chunk
#define NCH   (LL / CHUNK)       // 1024 chunks per batch
#define JPITCH 40                // words per jj row (32 l + 8 pad)
#define KTSZ  (8 * JPITCH)       // 320 words per kt slab
#define BUFW  (16 * KTSZ)        // 5120 words per buffer (20 KB)

// ---------------- device scratch ----------------
__device__ float  g_Ain [B_ * CIN * 2];     // [b][i*2 + r]
__device__ float  g_Aout[B_ * 2 * COUT];    // [b][r*256 + o]
__device__ __half g_Weff[B_ * COUT * CIN];  // [b][o][i]

// ---------------- helpers ----------------
__device__ __forceinline__ uint32_t pack_f16x2(float lo, float hi) {
    uint32_t r;  // second source -> low half
    asm("cvt.rn.f16x2.f32 %0, %1, %2;" : "=r"(r) : "f"(hi), "f"(lo));
    return r;
}

__device__ __forceinline__ void mma16816(float* c, const uint32_t* A, uint32_t b0, uint32_t b1) {
    asm volatile(
        "mma.sync.aligned.m16n8k16.row.col.f32.f16.f16.f32 "
        "{%0,%1,%2,%3}, {%4,%5,%6,%7}, {%8,%9}, {%0,%1,%2,%3};"
        : "+f"(c[0]), "+f"(c[1]), "+f"(c[2]), "+f"(c[3])
        : "r"(A[0]), "r"(A[1]), "r"(A[2]), "r"(A[3]), "r"(b0), "r"(b1));
}

// ---------------- prologue 1: adapter vectors (float4) ----------------
__global__ void lora_adapters_kernel(const float* __restrict__ g_out,
                                     const float* __restrict__ W_ain,
                                     const float* __restrict__ W_aout) {
    __shared__ float4 sg4[CINFO / 4];
    int bx = blockIdx.x;
    int b = bx >> 6;
    int kbase = (bx & 63) * 8;
    if (threadIdx.x < CINFO / 4)
        sg4[threadIdx.x] = ((const float4*)(g_out + b * CINFO))[threadIdx.x];
    __syncthreads();
    int w = threadIdx.x >> 5, lane = threadIdx.x & 31;
#pragma unroll
    for (int t = 0; t < 2; ++t) {
        int k = kbase + w * 2 + t;
        const float4* wi = (const float4*)(W_ain  + (size_t)k * CINFO);
        const float4* wo = (const float4*)(W_aout + (size_t)k * CINFO);
        float ai = 0.f, ao = 0.f;
#pragma unroll
        for (int i = lane; i < CINFO / 4; i += 32) {
            float4 gv = sg4[i];
            float4 a = wi[i], o = wo[i];
            ai += a.x * gv.x + a.y * gv.y + a.z * gv.z + a.w * gv.w;
            ao += o.x * gv.x + o.y * gv.y + o.z * gv.z + o.w * gv.w;
        }
#pragma unroll
        for (int off = 16; off; off >>= 1) {
            ai += __shfl_xor_sync(0xFFFFFFFFu, ai, off);
            ao += __shfl_xor_sync(0xFFFFFFFFu, ao, off);
        }
        if (lane == 0) {
            g_Ain [b * 512 + k] = ai;
            g_Aout[b * 512 + k] = ao;
        }
    }
}

// ---------------- prologue 2: effective weight (fp16) ----------------
__global__ void lora_weff_kernel(const float* __restrict__ W_main) {
    int o = blockIdx.x, b = blockIdx.y, i = threadIdx.x;
    float wm = W_main[o * CIN + i];
    float a0 = g_Ain [b * 512 + i * 2 + 0];
    float a1 = g_Ain [b * 512 + i * 2 + 1];
    float q0 = g_Aout[b * 512 + o];
    float q1 = g_Aout[b * 512 + COUT + o];
    g_Weff[(size_t)b * (COUT * CIN) + o * CIN + i] = __float2half(wm + q0 * a0 + q1 * a1);
}

// ---------------- main persistent GEMM (mma.sync / HMMA) ----------------
// 256 threads / 8 warps. Warp w owns cout rows [32w, 32w+32) (2 m-tiles),
// full N=32 (4 n-tiles), K=256 (16 kt) -> 128 MMAs/warp/chunk.
// A (Weff) fragments register-resident for the whole kernel.
//
// Pipeline per chunk: LDG.128 for chunk c+1 issued FIRST (raw float4 staged
// in regs), then the 4096-cyc MMA block on chunk c (hides LDG latency),
// then pack fp16 + STS.128 for c+1, epilogue STG, one __syncthreads.
//
// SMEM: word(kt, jj, l) = kt*320 + jj*40 + l (per buffer).
//   Consumer bank: (40q + 8nt + g) mod 32 = 8q+g+8nt mod 32 -> 32 distinct
//   banks over the warp for b0 (jj=q) and b1 (jj=q+4). Conflict-free.
//   STS.128: per phase of 8 lanes, words {jj*40 + 4c} c=0..7 -> 32 banks. CF.
__global__ void __launch_bounds__(256, 1)
lora_main_kernel(const float* __restrict__ x, const float* __restrict__ b_main,
                 float* __restrict__ out, int per_batch) {
    extern __shared__ uint32_t sm[];   // 2 * BUFW words = 40 KB
    const int tid = threadIdx.x;
    const int lane = tid & 31;
    const int w = tid >> 5;            // 0..7
    const int cta = blockIdx.x;
    const int b  = cta / per_batch;
    const int jb = cta % per_batch;
    const int s = (jb * NCH) / per_batch;
    const int e = ((jb + 1) * NCH) / per_batch;
    if (s >= e) return;

    const float* xb = x   + (size_t)b * ((size_t)CIN * LL);
    float*       ob = out + (size_t)b * ((size_t)COUT * LL);

    const int obase = w * 32;
    const int g = lane >> 3 | ((lane >> 2) & 1) * 0;  // placeholder, fixed below
    const int gg = lane >> 2;    // 0..7 (MMA row group)
    const int q  = lane & 3;     // 0..3

    // ---- A fragments (Weff) resident in registers ----
    uint32_t A0[16][4], A1[16][4];
    {
        const __half* Wb = g_Weff + (size_t)b * (COUT * CIN);
        const uint32_t* r00 = (const uint32_t*)(Wb + (size_t)(obase + gg)      * CIN);
        const uint32_t* r01 = (const uint32_t*)(Wb + (size_t)(obase + gg + 8)  * CIN);
        const uint32_t* r10 = (const uint32_t*)(Wb + (size_t)(obase + 16 + gg) * CIN);
        const uint32_t* r11 = (const uint32_t*)(Wb + (size_t)(obase + 24 + gg) * CIN);
#pragma unroll
        for (int kt = 0; kt < 16; ++kt) {
            A0[kt][0] = r00[kt * 8 + q];
            A0[kt][1] = r01[kt * 8 + q];
            A0[kt][2] = r00[kt * 8 + 4 + q];
            A0[kt][3] = r01[kt * 8 + 4 + q];
            A1[kt][0] = r10[kt * 8 + q];
            A1[kt][1] = r11[kt * 8 + q];
            A1[kt][2] = r10[kt * 8 + 4 + q];
            A1[kt][3] = r11[kt * 8 + 4 + q];
        }
    }
    const float bg00 = b_main[obase + gg];
    const float bg01 = b_main[obase + 8 + gg];
    const float bg10 = b_main[obase + 16 + gg];
    const float bg11 = b_main[obase + 24 + gg];

    // LDG staging: thread loads row-pair p = (lane>>3) + 4j, float4 at l = (lane&7)*4
    float4 sa[4], sb[4];
    const int c4 = (lane & 7) * 4;
    const int ph = lane >> 3;

    auto ldg_issue = [&](int chunk) {
        const float* base = xb + (size_t)chunk * CHUNK + c4;
#pragma unroll
        for (int j = 0; j < 4; ++j) {
            int row0 = w * 32 + 2 * (ph + 4 * j);
            sa[j] = *(const float4*)(base + (size_t)row0 * LL);
            sb[j] = *(const float4*)(base + (size_t)(row0 + 1) * LL);
        }
    };

    auto pack_sts = [&](int bufsel) {
        uint32_t* dst = sm + bufsel * BUFW;
#pragma unroll
        for (int j = 0; j < 4; ++j) {
            int p  = ph + 4 * j;
            int kt = 2 * w + (p >> 3);
            int jj = p & 7;
            uint4 v;
            v.x = pack_f16x2(sa[j].x, sb[j].x);
            v.y = pack_f16x2(sa[j].y, sb[j].y);
            v.z = pack_f16x2(sa[j].z, sb[j].z);
            v.w = pack_f16x2(sa[j].w, sb[j].w);
            *(uint4*)(dst + kt * KTSZ + jj * JPITCH + c4) = v;
        }
    };

    ldg_issue(s);
    pack_sts(0);
    __syncthreads();

    for (int c = s; c < e; ++c) {
        const int cb = (c - s) & 1;
        const bool more = (c + 1) < e;
        if (more) ldg_issue(c + 1);   // staged across the MMA block

        float acc0[4][4], acc1[4][4];
#pragma unroll
        for (int nt = 0; nt < 4; ++nt)
#pragma unroll
            for (int r = 0; r < 4; ++r) { acc0[nt][r] = 0.f; acc1[nt][r] = 0.f; }

        const uint32_t* buf = sm + cb * BUFW;
#pragma unroll
        for (int nt = 0; nt < 4; ++nt) {
            const int l = nt * 8 + gg;
            const uint32_t* p0 = buf + q * JPITCH + l;          // jj = q
            const uint32_t* p1 = buf + (q + 4) * JPITCH + l;    // jj = q+4
#pragma unroll
            for (int kt = 0; kt < 16; ++kt) {
                uint32_t b0 = p0[kt * KTSZ];
                uint32_t b1 = p1[kt * KTSZ];
                mma16816(acc0[nt], A0[kt], b0, b1);
                mma16816(acc1[nt], A1[kt], b0, b1);
            }
        }

        if (more) pack_sts(cb ^ 1);   // pack AFTER MMAs: LDG latency hidden

        // epilogue: bias + coalesced float2 stores
        {
            const size_t lc = (size_t)c * CHUNK + 2 * q;
            float* o00 = ob + (size_t)(obase + gg)      * LL + lc;
            float* o01 = ob + (size_t)(obase + gg + 8)  * LL + lc;
            float* o10 = ob + (size_t)(obase + 16 + gg) * LL + lc;
            float* o11 = ob + (size_t)(obase + 24 + gg) * LL + lc;
#pragma unroll
            for (int nt = 0; nt < 4; ++nt) {
                *(float2*)(o00 + nt * 8) = make_float2(acc0[nt][0] + bg00, acc0[nt][1] + bg00);
                *(float2*)(o01 + nt * 8) = make_float2(acc0[nt][2] + bg01, acc0[nt][3] + bg01);
                *(float2*)(o10 + nt * 8) = make_float2(acc1[nt][0] + bg10, acc1[nt][1] + bg10);
                *(float2*)(o11 + nt * 8) = make_float2(acc1[nt][2] + bg11, acc1[nt][3] + bg11);
            }
        }
        __syncthreads();
    }
    (void)g;
}

// ---------------- launch ----------------
extern "C" void kernel_launch(void* const* d_in, const int* in_sizes, int n_in,
                              void* d_out, int out_size) {
    const float* x      = (const float*)d_in[0];
    const float* g_out  = (const float*)d_in[1];
    const float* W_main = (const float*)d_in[2];
    const float* b_main = (const float*)d_in[3];
    const float* W_ain  = (const float*)d_in[4];
    const float* W_aout = (const float*)d_in[5];
    float* out = (float*)d_out;

    int dev = 0, sms = 148;
    cudaGetDevice(&dev);
    cudaDeviceGetAttribute(&sms, cudaDevAttrMultiProcessorCount, dev);
    int per_batch = sms / B_;
    if (per_batch < 1) per_batch = 1;
    if (per_batch > NCH) per_batch = NCH;

    size_t smem = 2ull * BUFW * sizeof(uint32_t);  // 40 KB
    cudaFuncSetAttribute(lora_main_kernel, cudaFuncAttributeMaxDynamicSharedMemorySize, (int)smem);

    lora_adapters_kernel<<<B_ * 64, 128>>>(g_out, W_ain, W_aout);
    lora_weff_kernel<<<dim3(COUT, B_), CIN>>>(W_main);
    lora_main_kernel<<<per_batch * B_, 256, smem>>>(x, b_main, out, per_batch);
}